// round 2
// baseline (speedup 1.0000x reference)
#include <cuda_runtime.h>
#include <cuda_bf16.h>

// Shapes (fixed by the problem): B=32, T=256, D=64, H=128, G=3H=384
#define B 32
#define T 256
#define D 64
#define H 128
#define G 384

// ---------------- scratch (device globals: allocation-free) ----------------
__device__ float g_sim[D * D];          // relu(E E^T)
__device__ float g_w[B * D];            // per-batch column weights of adj (mean over rows)
__device__ float g_vr[B * T * H];       // visit_repr (incl. time encoding)
__device__ float g_gi[B * T * G];       // gi = visit_repr @ W_ih^T + b_ih

// ---------------- packed f32x2 helpers ----------------
__device__ __forceinline__ unsigned long long ffma2(unsigned long long a,
                                                    unsigned long long b,
                                                    unsigned long long c) {
    unsigned long long d;
    asm("fma.rn.f32x2 %0, %1, %2, %3;" : "=l"(d) : "l"(a), "l"(b), "l"(c));
    return d;
}
__device__ __forceinline__ float2 u2f(unsigned long long v) {
    float2 r;
    asm("mov.b64 {%0, %1}, %2;" : "=f"(r.x), "=f"(r.y) : "l"(v));
    return r;
}
__device__ __forceinline__ float sigf(float x) {
    return 1.0f / (1.0f + __expf(-x));
}

// ---------------- kernel 0: sim = relu(E @ E^T), 64 blocks x 64 threads ----
__global__ void sim_kernel(const float* __restrict__ E) {
    __shared__ float EsT[128][65];   // transposed, padded: conflict-free
    int i = blockIdx.x;
    int tid = threadIdx.x;           // = j
    for (int idx = tid; idx < D * H; idx += 64) {
        int j = idx >> 7, k = idx & 127;
        EsT[k][j] = E[idx];
    }
    __syncthreads();
    float acc = 0.f;
#pragma unroll 8
    for (int k = 0; k < H; k++)
        acc += EsT[k][i] * EsT[k][tid];   // EsT[k][i] broadcast, EsT[k][tid] coalesced
    g_sim[i * D + tid] = fmaxf(acc, 0.f);
}

// ---------------- kernel 1: per-batch w[b,j], 32 blocks x 64 threads -------
__global__ void wcoef_kernel(const float* __restrict__ mm) {
    __shared__ float p[D], rs[D];
    int b = blockIdx.x, j = threadIdx.x;
    const float* mb = mm + b * T * D;
    float s = 0.f;
    for (int t = 0; t < T; t++) s += mb[t * D + j];     // coalesced over j
    p[j] = 1.f - s * (1.f / (float)T);
    __syncthreads();
    // rs[i] = sum_j p_i p_j sim_ij + 1   (thread j plays row i)
    float q = 0.f;
    for (int jj = 0; jj < D; jj++) q += p[jj] * g_sim[j * D + jj];
    rs[j] = fmaxf(p[j] * q + 1.f, 1e-6f);
    __syncthreads();
    // w[j] = (1/D) * sum_i (p_i p_j sim_ij + delta_ij) / rs_i
    float acc = 0.f;
    for (int i = 0; i < D; i++) acc += p[i] * g_sim[i * D + j] / rs[i];
    g_w[b * D + j] = (p[j] * acc + 1.f / rs[j]) * (1.f / (float)D);
}

// ---------------- kernel 2a: visit_repr = c @ E + time_enc -----------------
// grid (8 t-tiles, 32 batches), 256 threads. 32 t per tile.
__global__ __launch_bounds__(256) void vr_kernel(
    const float* __restrict__ x, const float* __restrict__ mm,
    const float* __restrict__ vt, const float* __restrict__ E) {
    __shared__ float Es[D * H];      // 32 KB
    __shared__ float cs[32 * D];     // 8 KB
    __shared__ float tv[32];
    int b = blockIdx.y, t0 = blockIdx.x * 32, tid = threadIdx.x;

    for (int idx = tid; idx < D * H; idx += 256) Es[idx] = E[idx];
    int base = b * T * D + t0 * D;
    for (int idx = tid; idx < 32 * D; idx += 256) {
        int j = idx & (D - 1);
        cs[idx] = x[base + idx] * (1.f - mm[base + idx]) * g_w[b * D + j];
    }
    if (tid < 32) tv[tid] = vt[b * T + t0 + tid];
    __syncthreads();

    int warp = tid >> 5, lane = tid & 31;
    float acc[4][4] = {};
#pragma unroll 4
    for (int j = 0; j < D; j++) {
        float e0 = Es[j * H + lane];
        float e1 = Es[j * H + lane + 32];
        float e2 = Es[j * H + lane + 64];
        float e3 = Es[j * H + lane + 96];
#pragma unroll
        for (int q = 0; q < 4; q++) {
            float c = cs[(warp * 4 + q) * D + j];   // broadcast
            acc[q][0] += c * e0; acc[q][1] += c * e1;
            acc[q][2] += c * e2; acc[q][3] += c * e3;
        }
    }
    const float NEGC = -0.14391156831212787f;  // -ln(10000)/64
#pragma unroll
    for (int q = 0; q < 4; q++) {
        int tt = warp * 4 + q;
        float t = tv[tt];
        float* o = g_vr + (b * T + t0 + tt) * H;
#pragma unroll
        for (int m = 0; m < 4; m++) {
            int h = lane + 32 * m;
            int hm = (h < 64) ? h : h - 64;
            float ang = t * expf(NEGC * (float)hm);
            float te = (h < 64) ? sinf(ang) : cosf(ang);
            o[h] = acc[q][m] + te;
        }
    }
}

// ---------------- kernel 2b: gi = vr @ W_ih^T + b_ih -----------------------
// grid (256 bt-tiles, 3 g-chunks of 128), 256 threads, dyn smem 82432 B.
extern __shared__ float sm2b[];
__global__ __launch_bounds__(256) void gi_kernel(
    const float* __restrict__ wih, const float* __restrict__ bih) {
    float* vrs = sm2b;                  // 32 x 128
    float* Wt = sm2b + 32 * H;          // 128 x (128+1) transposed, padded
    int bt0 = blockIdx.x * 32, g0 = blockIdx.y * 128, tid = threadIdx.x;

    for (int idx = tid; idx < 32 * H; idx += 256) vrs[idx] = g_vr[bt0 * H + idx];
    for (int idx = tid; idx < 128 * H; idx += 256) {
        int gg = idx >> 7, k = idx & 127;
        Wt[k * 129 + gg] = wih[(g0 + gg) * H + k];   // conflict-free (129 stride)
    }
    __syncthreads();

    int warp = tid >> 5, lane = tid & 31;
    float acc[4][4] = {};
#pragma unroll 4
    for (int k = 0; k < H; k++) {
        float w0 = Wt[k * 129 + lane];
        float w1 = Wt[k * 129 + lane + 32];
        float w2 = Wt[k * 129 + lane + 64];
        float w3 = Wt[k * 129 + lane + 96];
#pragma unroll
        for (int q = 0; q < 4; q++) {
            float v = vrs[(warp * 4 + q) * H + k];  // broadcast
            acc[q][0] += v * w0; acc[q][1] += v * w1;
            acc[q][2] += v * w2; acc[q][3] += v * w3;
        }
    }
#pragma unroll
    for (int q = 0; q < 4; q++) {
        int tt = warp * 4 + q;
        float* o = g_gi + (bt0 + tt) * G + g0;
#pragma unroll
        for (int m = 0; m < 4; m++) {
            int g = lane + 32 * m;
            o[g] = acc[q][m] + bih[g0 + g];
        }
    }
}

// ---------------- kernel 3: GRU recurrence ---------------------------------
// 32 blocks (one per batch), 384 threads. W_hh in registers (f32x2-packed),
// h broadcast from smem, gh via packed fma.rn.f32x2.
__global__ __launch_bounds__(384, 1) void gru_kernel(
    const float* __restrict__ whh, const float* __restrict__ bhh,
    const int* __restrict__ lengths, float* __restrict__ out) {
    __shared__ __align__(16) float hs[H];
    __shared__ float ghs[G];
    int b = blockIdx.x, g = threadIdx.x;

    // Load W_hh row g as 64 packed f32x2 values into registers
    unsigned long long w[64];
    const ulonglong2* wr = reinterpret_cast<const ulonglong2*>(whh + g * H);
#pragma unroll
    for (int i = 0; i < 32; i++) {
        ulonglong2 v = wr[i];
        w[2 * i] = v.x; w[2 * i + 1] = v.y;
    }
    float bg = bhh[g];
    int len = lengths[b];
    if (g < H) hs[g] = 0.f;
    __syncthreads();

    const float* gib = g_gi + b * T * G;
    float* ob = out + b * T * H;

    for (int t = 0; t < T; t++) {
        float gir = 0.f, giz = 0.f, gin = 0.f;
        if (g < H) {   // prefetch gi early: latency hidden under the gemv
            const float* gp = gib + t * G;
            gir = gp[g]; giz = gp[H + g]; gin = gp[2 * H + g];
        }
        const ulonglong2* h2 = reinterpret_cast<const ulonglong2*>(hs);
        unsigned long long a0 = 0ull, a1 = 0ull, a2 = 0ull, a3 = 0ull;
#pragma unroll
        for (int i = 0; i < 16; i++) {
            ulonglong2 hv0 = h2[2 * i];        // LDS.128 broadcast
            ulonglong2 hv1 = h2[2 * i + 1];
            a0 = ffma2(w[4 * i + 0], hv0.x, a0);
            a1 = ffma2(w[4 * i + 1], hv0.y, a1);
            a2 = ffma2(w[4 * i + 2], hv1.x, a2);
            a3 = ffma2(w[4 * i + 3], hv1.y, a3);
        }
        float2 f0 = u2f(a0), f1 = u2f(a1), f2 = u2f(a2), f3 = u2f(a3);
        ghs[g] = f0.x + f0.y + f1.x + f1.y + f2.x + f2.y + f3.x + f3.y + bg;
        __syncthreads();
        if (g < H) {
            float r = sigf(gir + ghs[g]);
            float z = sigf(giz + ghs[H + g]);
            float n = tanhf(gin + r * ghs[2 * H + g]);
            float hn = (1.f - z) * n + z * hs[g];
            hs[g] = hn;
            ob[t * H + g] = (t < len) ? hn : 0.f;   // pad_packed masking
        }
        __syncthreads();
    }
}

// ---------------- launcher -------------------------------------------------
extern "C" void kernel_launch(void* const* d_in, const int* in_sizes, int n_in,
                              void* d_out, int out_size) {
    const float* x   = (const float*)d_in[0];
    const float* mm  = (const float*)d_in[1];
    const float* vt  = (const float*)d_in[2];
    // d_in[3] = time_delta (unused by reference)
    const int*   len = (const int*)d_in[4];
    const float* E   = (const float*)d_in[5];
    const float* wih = (const float*)d_in[6];
    const float* whh = (const float*)d_in[7];
    const float* bih = (const float*)d_in[8];
    const float* bhh = (const float*)d_in[9];
    float* out = (float*)d_out;

    size_t sm2b_bytes = (32 * H + 128 * 129) * sizeof(float);   // 82432
    cudaFuncSetAttribute(gi_kernel, cudaFuncAttributeMaxDynamicSharedMemorySize,
                         (int)sm2b_bytes);

    sim_kernel<<<D, 64>>>(E);
    wcoef_kernel<<<B, 64>>>(mm);
    vr_kernel<<<dim3(T / 32, B), 256>>>(x, mm, vt, E);
    gi_kernel<<<dim3(B * T / 32, 3), 256, sm2b_bytes>>>(wih, bih);
    gru_kernel<<<B, 384>>>(whh, bhh, len, out);
}

// round 3
// speedup vs baseline: 1.0148x; 1.0148x over previous
#include <cuda_runtime.h>
#include <cuda_bf16.h>

// Shapes (fixed): B=32, T=256, D=64, H=128, G=3H=384
#define B 32
#define T 256
#define D 64
#define H 128
#define G 384

// ---------------- scratch (device globals: allocation-free) ----------------
__device__ float g_sim[D * D];
__device__ float g_w[B * D];
__device__ float g_vr[B * T * H];
__device__ float g_gi[B * T * G];

// ---------------- packed f32x2 helpers ----------------
__device__ __forceinline__ unsigned long long ffma2(unsigned long long a,
                                                    unsigned long long b,
                                                    unsigned long long c) {
    unsigned long long d;
    asm("fma.rn.f32x2 %0, %1, %2, %3;" : "=l"(d) : "l"(a), "l"(b), "l"(c));
    return d;
}
__device__ __forceinline__ unsigned long long addf2(unsigned long long a,
                                                    unsigned long long b) {
    unsigned long long d;
    asm("add.rn.f32x2 %0, %1, %2;" : "=l"(d) : "l"(a), "l"(b));
    return d;
}
__device__ __forceinline__ float2 u2f(unsigned long long v) {
    float2 r;
    asm("mov.b64 {%0, %1}, %2;" : "=f"(r.x), "=f"(r.y) : "l"(v));
    return r;
}
__device__ __forceinline__ float sigf(float x) {
    return 1.0f / (1.0f + __expf(-x));
}

// ---------------- kernel 0: sim = relu(E @ E^T) ----------------------------
__global__ void sim_kernel(const float* __restrict__ E) {
    __shared__ float EsT[128][65];
    int i = blockIdx.x;
    int tid = threadIdx.x;
    for (int idx = tid; idx < D * H; idx += 64) {
        int j = idx >> 7, k = idx & 127;
        EsT[k][j] = E[idx];
    }
    __syncthreads();
    float acc = 0.f;
#pragma unroll 8
    for (int k = 0; k < H; k++)
        acc += EsT[k][i] * EsT[k][tid];
    g_sim[i * D + tid] = fmaxf(acc, 0.f);
}

// ---------------- kernel 1: per-batch w[b,j], 32 blocks x 256 threads ------
__global__ __launch_bounds__(256) void wcoef_kernel(const float* __restrict__ mm) {
    __shared__ float part[4][D];
    __shared__ float p[D], rs[D];
    int b = blockIdx.x, tid = threadIdx.x;
    int j = tid & (D - 1), c = tid >> 6;       // 4 t-chunks of 64
    const float* mb = mm + b * T * D;
    float s = 0.f;
#pragma unroll 8
    for (int t = c * 64; t < (c + 1) * 64; t++) s += mb[t * D + j];
    part[c][j] = s;
    __syncthreads();
    if (tid < D) {
        float tot = part[0][j] + part[1][j] + part[2][j] + part[3][j];
        p[j] = 1.f - tot * (1.f / (float)T);
    }
    __syncthreads();
    if (tid < D) {
        float q = 0.f;
#pragma unroll 8
        for (int jj = 0; jj < D; jj++) q += p[jj] * g_sim[j * D + jj];
        rs[j] = fmaxf(p[j] * q + 1.f, 1e-6f);
    }
    __syncthreads();
    if (tid < D) {
        float acc = 0.f;
#pragma unroll 8
        for (int i = 0; i < D; i++) acc += p[i] * g_sim[i * D + j] / rs[i];
        g_w[b * D + j] = (p[j] * acc + 1.f / rs[j]) * (1.f / (float)D);
    }
}

// ---------------- kernel 2a: visit_repr = c @ E + time_enc -----------------
__global__ __launch_bounds__(256) void vr_kernel(
    const float* __restrict__ x, const float* __restrict__ mm,
    const float* __restrict__ vt, const float* __restrict__ E) {
    __shared__ float Es[D * H];
    __shared__ float cs[32 * D];
    __shared__ float tv[32];
    __shared__ float freqs[64];
    int b = blockIdx.y, t0 = blockIdx.x * 32, tid = threadIdx.x;

    const float NEGC = -0.14391156831212787f;  // -ln(10000)/64
    if (tid < 64) freqs[tid] = __expf(NEGC * (float)tid);
    for (int idx = tid; idx < D * H; idx += 256) Es[idx] = E[idx];
    int base = b * T * D + t0 * D;
    for (int idx = tid; idx < 32 * D; idx += 256) {
        int j = idx & (D - 1);
        cs[idx] = x[base + idx] * (1.f - mm[base + idx]) * g_w[b * D + j];
    }
    if (tid < 32) tv[tid] = vt[b * T + t0 + tid];
    __syncthreads();

    int warp = tid >> 5, lane = tid & 31;
    float acc[4][4] = {};
#pragma unroll 4
    for (int j = 0; j < D; j++) {
        float e0 = Es[j * H + lane];
        float e1 = Es[j * H + lane + 32];
        float e2 = Es[j * H + lane + 64];
        float e3 = Es[j * H + lane + 96];
#pragma unroll
        for (int q = 0; q < 4; q++) {
            float c = cs[(warp * 4 + q) * D + j];
            acc[q][0] += c * e0; acc[q][1] += c * e1;
            acc[q][2] += c * e2; acc[q][3] += c * e3;
        }
    }
#pragma unroll
    for (int q = 0; q < 4; q++) {
        int tt = warp * 4 + q;
        float t = tv[tt];
        float* o = g_vr + (b * T + t0 + tt) * H;
#pragma unroll
        for (int m = 0; m < 4; m++) {
            int h = lane + 32 * m;
            int hm = (h < 64) ? h : h - 64;
            float ang = t * freqs[hm];
            float te = (h < 64) ? sinf(ang) : cosf(ang);
            o[h] = acc[q][m] + te;
        }
    }
}

// ---------------- kernel 2b: gi = vr @ W_ih^T + b_ih (packed FFMA2) --------
// grid (128 bt-tiles of 64, 3 g-chunks of 128), 256 threads.
// W stored as float2 over k-pairs so the FFMA2 'b' operand is a raw LDS.64
// broadcast of vr — no packing movs. Thread owns 8 bt rows x 4 strided g.
#define W2STRIDE 130
extern __shared__ float sm2b[];
__global__ __launch_bounds__(256) void gi_kernel(
    const float* __restrict__ wih, const float* __restrict__ bih) {
    float* vrs = sm2b;                                     // 64 x 128 floats
    float2* W2 = reinterpret_cast<float2*>(sm2b + 64 * H); // [kp][g], stride 130
    int bt0 = blockIdx.x * 64, g0 = blockIdx.y * 128, tid = threadIdx.x;

    for (int idx = tid; idx < 64 * H; idx += 256) vrs[idx] = g_vr[bt0 * H + idx];
    // fill W2: idx = g*64 + kp  (gmem-coalesced float2 reads)
    const float2* wih2 = reinterpret_cast<const float2*>(wih + g0 * H);
    for (int idx = tid; idx < 128 * 64; idx += 256) {
        int g = idx >> 6, kp = idx & 63;
        W2[kp * W2STRIDE + g] = wih2[g * 64 + kp];
    }
    __syncthreads();

    int warp = tid >> 5, lane = tid & 31;
    const float* vrow = vrs + warp * 8 * H;                // 8 rows per warp
    unsigned long long acc[8][4] = {};
#pragma unroll 2
    for (int kp = 0; kp < 64; kp++) {
        const unsigned long long* wrow =
            reinterpret_cast<const unsigned long long*>(W2 + kp * W2STRIDE);
        unsigned long long w0 = wrow[lane];
        unsigned long long w1 = wrow[lane + 32];
        unsigned long long w2 = wrow[lane + 64];
        unsigned long long w3 = wrow[lane + 96];
#pragma unroll
        for (int q = 0; q < 8; q++) {
            unsigned long long v =
                *reinterpret_cast<const unsigned long long*>(vrow + q * H + 2 * kp);
            acc[q][0] = ffma2(w0, v, acc[q][0]);
            acc[q][1] = ffma2(w1, v, acc[q][1]);
            acc[q][2] = ffma2(w2, v, acc[q][2]);
            acc[q][3] = ffma2(w3, v, acc[q][3]);
        }
    }
#pragma unroll
    for (int q = 0; q < 8; q++) {
        float* o = g_gi + (bt0 + warp * 8 + q) * G + g0;
#pragma unroll
        for (int m = 0; m < 4; m++) {
            float2 f = u2f(acc[q][m]);
            int g = lane + 32 * m;
            o[g] = f.x + f.y + bih[g0 + g];
        }
    }
}

// ---------------- kernel 3: GRU recurrence ---------------------------------
// 32 blocks (one per batch), 384 threads, W_hh row in registers (f32x2),
// h broadcast from smem via LDS.128, gh via packed FFMA2. Fast gate math.
__global__ __launch_bounds__(384, 1) void gru_kernel(
    const float* __restrict__ whh, const float* __restrict__ bhh,
    const int* __restrict__ lengths, float* __restrict__ out) {
    __shared__ __align__(16) float hs[H];
    __shared__ float ghs[G];
    int b = blockIdx.x, g = threadIdx.x;

    unsigned long long w[64];
    const ulonglong2* wr = reinterpret_cast<const ulonglong2*>(whh + g * H);
#pragma unroll
    for (int i = 0; i < 32; i++) {
        ulonglong2 v = wr[i];
        w[2 * i] = v.x; w[2 * i + 1] = v.y;
    }
    float bg = bhh[g];
    int len = lengths[b];
    if (g < H) hs[g] = 0.f;

    const float* gib = g_gi + b * T * G;
    float* ob = out + b * T * H;

    // prefetch step-0 gates input
    float gir = 0.f, giz = 0.f, gin = 0.f;
    if (g < H) { gir = gib[g]; giz = gib[H + g]; gin = gib[2 * H + g]; }
    __syncthreads();

    for (int t = 0; t < T; t++) {
        const ulonglong2* h2 = reinterpret_cast<const ulonglong2*>(hs);
        unsigned long long a0 = 0ull, a1 = 0ull;
#pragma unroll
        for (int i = 0; i < 32; i++) {
            ulonglong2 hv = h2[i];                 // LDS.128 broadcast
            a0 = ffma2(w[2 * i], hv.x, a0);
            a1 = ffma2(w[2 * i + 1], hv.y, a1);
        }
        float2 f = u2f(addf2(a0, a1));
        ghs[g] = f.x + f.y + bg;

        // prefetch next step's gi before the barrier (hidden under sync+gates)
        float nr = 0.f, nz = 0.f, nn = 0.f;
        if (g < H && t + 1 < T) {
            const float* q = gib + (t + 1) * G;
            nr = q[g]; nz = q[H + g]; nn = q[2 * H + g];
        }
        __syncthreads();
        if (g < H) {
            float r = sigf(gir + ghs[g]);
            float z = sigf(giz + ghs[H + g]);
            float a = gin + r * ghs[2 * H + g];
            float n = 1.f - 2.f / (__expf(2.f * a) + 1.f);  // tanh, NaN-safe
            float hn = n + z * (hs[g] - n);
            hs[g] = hn;
            ob[t * H + g] = (t < len) ? hn : 0.f;
        }
        __syncthreads();
        gir = nr; giz = nz; gin = nn;
    }
}

// ---------------- launcher -------------------------------------------------
extern "C" void kernel_launch(void* const* d_in, const int* in_sizes, int n_in,
                              void* d_out, int out_size) {
    const float* x   = (const float*)d_in[0];
    const float* mm  = (const float*)d_in[1];
    const float* vt  = (const float*)d_in[2];
    const int*   len = (const int*)d_in[4];
    const float* E   = (const float*)d_in[5];
    const float* wih = (const float*)d_in[6];
    const float* whh = (const float*)d_in[7];
    const float* bih = (const float*)d_in[8];
    const float* bhh = (const float*)d_in[9];
    float* out = (float*)d_out;

    size_t sm2b_bytes = 64 * H * sizeof(float) + 64 * W2STRIDE * sizeof(float2);
    static int attr_set = 0;
    cudaFuncSetAttribute(gi_kernel, cudaFuncAttributeMaxDynamicSharedMemorySize,
                         (int)sm2b_bytes);
    (void)attr_set;

    sim_kernel<<<D, 64>>>(E);
    wcoef_kernel<<<B, 256>>>(mm);
    vr_kernel<<<dim3(T / 32, B), 256>>>(x, mm, vt, E);
    gi_kernel<<<dim3(B * T / 64, 3), 256, sm2b_bytes>>>(wih, bih);
    gru_kernel<<<B, 384>>>(whh, bhh, len, out);
}